// round 2
// baseline (speedup 1.0000x reference)
#include <cuda_runtime.h>
#include <cuda_bf16.h>
#include <cstddef>

// Triplet loss with class-balanced weights.
// batch: [4096,128] f32; triplets: [T,3] i32; labels: [4096] i32; img_num_per_cls: [C] f32
// out[0] = mean( relu(|a-p|^2 - |a-n|^2 + 1) * (sum(img)/img[label[a]]) )

constexpr int D        = 128;   // feature dim
constexpr int NBLOCKS  = 1184;  // 148 SMs * 8 blocks
constexpr int NTHREADS = 256;   // 8 warps/block -> 2048 thr/SM (full occupancy)

__device__ float g_partials[NBLOCKS];

__global__ __launch_bounds__(NTHREADS, 8)
void trip_partial_kernel(const float* __restrict__ batch,
                         const int*   __restrict__ triplets,
                         const int*   __restrict__ labels,
                         const float* __restrict__ img,
                         int T)
{
    const int lane = threadIdx.x & 31;
    const int wid  = threadIdx.x >> 5;
    const int gw   = blockIdx.x * (NTHREADS / 32) + wid;
    const int nw   = NBLOCKS * (NTHREADS / 32);

    float acc = 0.0f;

    for (int t = gw; t < T; t += nw) {
        // uniform across the warp -> single broadcast request each
        const int ia  = __ldg(&triplets[3 * t + 0]);
        const int ip  = __ldg(&triplets[3 * t + 1]);
        const int in_ = __ldg(&triplets[3 * t + 2]);

        const float4* __restrict__ A = reinterpret_cast<const float4*>(batch + (size_t)ia  * D);
        const float4* __restrict__ P = reinterpret_cast<const float4*>(batch + (size_t)ip  * D);
        const float4* __restrict__ N = reinterpret_cast<const float4*>(batch + (size_t)in_ * D);

        const float4 a = __ldg(A + lane);
        const float4 p = __ldg(P + lane);
        const float4 n = __ldg(N + lane);

        float d = 0.0f, dx;
        dx = a.x - p.x; d = fmaf(dx, dx, d);
        dx = a.y - p.y; d = fmaf(dx, dx, d);
        dx = a.z - p.z; d = fmaf(dx, dx, d);
        dx = a.w - p.w; d = fmaf(dx, dx, d);
        dx = a.x - n.x; d = fmaf(dx, -dx, d);
        dx = a.y - n.y; d = fmaf(dx, -dx, d);
        dx = a.z - n.z; d = fmaf(dx, -dx, d);
        dx = a.w - n.w; d = fmaf(dx, -dx, d);

        // warp reduce: d_ap - d_an
        d += __shfl_down_sync(0xffffffffu, d, 16);
        d += __shfl_down_sync(0xffffffffu, d, 8);
        d += __shfl_down_sync(0xffffffffu, d, 4);
        d += __shfl_down_sync(0xffffffffu, d, 2);
        d += __shfl_down_sync(0xffffffffu, d, 1);

        if (lane == 0) {
            const float loss = d + 1.0f;  // MARGIN = 1.0
            if (loss > 0.0f) {
                // factor 'total' out: accumulate loss / img[cls], scale by total at end
                acc += loss / __ldg(&img[__ldg(&labels[ia])]);
            }
        }
    }

    // block reduce (only lane 0 of each warp holds a value)
    __shared__ float sacc[NTHREADS / 32];
    if (lane == 0) sacc[wid] = acc;
    __syncthreads();
    if (threadIdx.x < (NTHREADS / 32)) {
        float v = sacc[threadIdx.x];
        v += __shfl_down_sync(0xffu, v, 4);
        v += __shfl_down_sync(0xffu, v, 2);
        v += __shfl_down_sync(0xffu, v, 1);
        if (threadIdx.x == 0) g_partials[blockIdx.x] = v;
    }
}

__global__ void finalize_kernel(const float* __restrict__ img,
                                float* __restrict__ out,
                                int T, int C)
{
    __shared__ float s1[256];
    __shared__ float s2[256];
    const int tid = threadIdx.x;

    float a = 0.0f, b = 0.0f;
    for (int i = tid; i < NBLOCKS; i += 256) a += g_partials[i];
    for (int i = tid; i < C; i += 256) b += img[i];
    s1[tid] = a;
    s2[tid] = b;
    __syncthreads();

    for (int s = 128; s > 0; s >>= 1) {
        if (tid < s) {
            s1[tid] += s1[tid + s];
            s2[tid] += s2[tid + s];
        }
        __syncthreads();
    }
    if (tid == 0) {
        out[0] = s1[0] * s2[0] / (float)T;  // mean, with total = sum(img) applied
    }
}

extern "C" void kernel_launch(void* const* d_in, const int* in_sizes, int n_in,
                              void* d_out, int out_size)
{
    const float* batch    = (const float*)d_in[0];
    const int*   triplets = (const int*)  d_in[1];
    const int*   labels   = (const int*)  d_in[2];
    const float* img      = (const float*)d_in[3];
    float*       out      = (float*)d_out;

    const int T = in_sizes[1] / 3;
    const int C = in_sizes[3];

    trip_partial_kernel<<<NBLOCKS, NTHREADS>>>(batch, triplets, labels, img, T);
    finalize_kernel<<<1, 256>>>(img, out, T, C);
}